// round 1
// baseline (speedup 1.0000x reference)
#include <cuda_runtime.h>

#define IMG_H 1024
#define IMG_W 1024
#define TW 32      // tile width  (output)
#define TH 64      // tile height (output)
#define HALO 2     // pad = 5/2
#define BLK_Y 16   // block = 32 x 16 = 512 threads

__device__ __forceinline__ int reflect_idx(int g, int n) {
    // single reflection is enough for pad=2
    g = (g < 0) ? -g : g;
    g = (g >= n) ? (2 * n - 2 - g) : g;
    return g;
}

__global__ __launch_bounds__(TW * BLK_Y, 4)
void box5_kernel(const float* __restrict__ in, float* __restrict__ out) {
    __shared__ float tile[TH + 2 * HALO][TW + 2 * HALO];  // 68 x 36
    __shared__ float hsum[TH + 2 * HALO][TW];             // 68 x 32

    const int plane = blockIdx.z;                          // N*C planes
    const float* __restrict__ p = in  + (size_t)plane * IMG_H * IMG_W;
    float* __restrict__       o = out + (size_t)plane * IMG_H * IMG_W;

    const int x0 = blockIdx.x * TW;
    const int y0 = blockIdx.y * TH;
    const int tx = threadIdx.x;   // 0..31
    const int ty = threadIdx.y;   // 0..15

    // ---- Load halo tile (68 rows x 36 cols), coalesced along x ----
    const int gx  = reflect_idx(x0 + tx - HALO, IMG_W);
    const int gx2 = reflect_idx(x0 + tx + TW - HALO, IMG_W);  // only used by tx<4
    #pragma unroll
    for (int r = ty; r < TH + 2 * HALO; r += BLK_Y) {
        const int gy = reflect_idx(y0 + r - HALO, IMG_H);
        const float* row = p + (size_t)gy * IMG_W;
        tile[r][tx] = row[gx];
        if (tx < 2 * HALO) {
            tile[r][tx + TW] = row[gx2];
        }
    }
    __syncthreads();

    // ---- Horizontal 5-tap sums: hsum[r][x] = sum tile[r][x..x+4] ----
    #pragma unroll
    for (int r = ty; r < TH + 2 * HALO; r += BLK_Y) {
        float s = tile[r][tx]     + tile[r][tx + 1] + tile[r][tx + 2]
                + tile[r][tx + 3] + tile[r][tx + 4];
        hsum[r][tx] = s;
    }
    __syncthreads();

    // ---- Vertical 5-tap sums: each thread writes 4 output rows ----
    const float inv25 = 1.0f / 25.0f;
    #pragma unroll
    for (int k = 0; k < TH / BLK_Y; k++) {
        const int y = ty + k * BLK_Y;                 // 0..63
        float s = hsum[y][tx]     + hsum[y + 1][tx] + hsum[y + 2][tx]
                + hsum[y + 3][tx] + hsum[y + 4][tx];
        o[(size_t)(y0 + y) * IMG_W + (x0 + tx)] = s * inv25;
    }
}

extern "C" void kernel_launch(void* const* d_in, const int* in_sizes, int n_in,
                              void* d_out, int out_size) {
    const float* image = (const float*)d_in[0];
    float* out = (float*)d_out;

    // 16 * 3 = 48 planes of 1024x1024
    const int planes = in_sizes[0] / (IMG_H * IMG_W);

    dim3 block(TW, BLK_Y);
    dim3 grid(IMG_W / TW, IMG_H / TH, planes);
    box5_kernel<<<grid, block>>>(image, out);
}

// round 3
// speedup vs baseline: 1.4432x; 1.4432x over previous
#include <cuda_runtime.h>

#define IMG_H 1024
#define IMG_W 1024
#define STRIP_W 128      // per-warp strip width  (32 lanes x float4)
#define STRIP_H 64       // per-warp strip height (output rows)
#define WARPS   4        // warps per block, each an independent y-strip

__device__ __forceinline__ int reflect_idx(int g, int n) {
    g = (g < 0) ? -g : g;
    g = (g >= n) ? (2 * n - 2 - g) : g;
    return g;
}

// Horizontal 5-tap sum for one row: lane holds v = row[xb..xb+3].
// Halo from neighbor lanes via shuffle; warp-edge lanes patch from gmem.
__device__ __forceinline__ float4 hsum_row(const float* __restrict__ row,
                                           int xb, int lane,
                                           int xl2, int xl1, int xr0, int xr1) {
    const float4 v = *reinterpret_cast<const float4*>(row + xb);

    float lz = __shfl_up_sync(0xFFFFFFFFu, v.z, 1);   // e[x-2]
    float lw = __shfl_up_sync(0xFFFFFFFFu, v.w, 1);   // e[x-1]
    float rx = __shfl_down_sync(0xFFFFFFFFu, v.x, 1); // e[x+4]
    float ry = __shfl_down_sync(0xFFFFFFFFu, v.y, 1); // e[x+5]

    if (lane == 0)  { lz = row[xl2]; lw = row[xl1]; }
    if (lane == 31) { rx = row[xr0]; ry = row[xr1]; }

    const float c  = v.y + v.z;          // shared middle pair
    const float s4 = v.x + c + v.w;      // v.x+v.y+v.z+v.w

    float4 h;
    h.x = lz + lw + v.x + c;             // e-2+e-1+e0+e1+e2
    h.y = lw + s4;                       // e-1+e0+e1+e2+e3
    h.z = s4 + rx;                       // e0+e1+e2+e3+e4
    h.w = c + v.w + rx + ry;             // e1+e2+e3+e4+e5
    return h;
}

__global__ __launch_bounds__(32 * WARPS)
void box5_kernel(const float* __restrict__ in, float* __restrict__ out) {
    const int lane  = threadIdx.x;
    const int plane = blockIdx.z;
    const float* __restrict__ p = in  + (size_t)plane * IMG_H * IMG_W;
    float* __restrict__       o = out + (size_t)plane * IMG_H * IMG_W;

    const int xt = blockIdx.x * STRIP_W;            // strip left edge
    const int xb = xt + lane * 4;                   // this lane's 4 columns
    const int y0 = (blockIdx.y * WARPS + threadIdx.y) * STRIP_H;

    // x-halo source columns (reflect only matters at image edges)
    const int xl2 = reflect_idx(xt - 2, IMG_W);
    const int xl1 = reflect_idx(xt - 1, IMG_W);
    const int xr0 = reflect_idx(xt + STRIP_W,     IMG_W);
    const int xr1 = reflect_idx(xt + STRIP_W + 1, IMG_W);

    // Prime the vertical window with hsums of input rows y0-2 .. y0+1
    float4 h0, h1, h2, h3;
    {
        const int gy0 = reflect_idx(y0 - 2, IMG_H);
        const int gy1 = reflect_idx(y0 - 1, IMG_H);
        h0 = hsum_row(p + (size_t)gy0 * IMG_W, xb, lane, xl2, xl1, xr0, xr1);
        h1 = hsum_row(p + (size_t)gy1 * IMG_W, xb, lane, xl2, xl1, xr0, xr1);
        h2 = hsum_row(p + (size_t)(y0 + 0) * IMG_W, xb, lane, xl2, xl1, xr0, xr1);
        h3 = hsum_row(p + (size_t)(y0 + 1) * IMG_W, xb, lane, xl2, xl1, xr0, xr1);
    }

    float4 vs;
    vs.x = h0.x + h1.x + h2.x + h3.x;
    vs.y = h0.y + h1.y + h2.y + h3.y;
    vs.z = h0.z + h1.z + h2.z + h3.z;
    vs.w = h0.w + h1.w + h2.w + h3.w;

    const float inv25 = 1.0f / 25.0f;

    #pragma unroll 8
    for (int r = 0; r < STRIP_H; ++r) {
        const int gy = reflect_idx(y0 + r + 2, IMG_H);   // bottom row of window
        const float4 h4 = hsum_row(p + (size_t)gy * IMG_W, xb, lane,
                                   xl2, xl1, xr0, xr1);

        // window sum = vs (4 rows) + h4
        float4 ov;
        ov.x = (vs.x + h4.x) * inv25;
        ov.y = (vs.y + h4.y) * inv25;
        ov.z = (vs.z + h4.z) * inv25;
        ov.w = (vs.w + h4.w) * inv25;
        *reinterpret_cast<float4*>(o + (size_t)(y0 + r) * IMG_W + xb) = ov;

        // slide: drop oldest row, add newest
        vs.x += h4.x - h0.x;
        vs.y += h4.y - h0.y;
        vs.z += h4.z - h0.z;
        vs.w += h4.w - h0.w;
        h0 = h1; h1 = h2; h2 = h3; h3 = h4;
    }
}

extern "C" void kernel_launch(void* const* d_in, const int* in_sizes, int n_in,
                              void* d_out, int out_size) {
    const float* image = (const float*)d_in[0];
    float* out = (float*)d_out;

    const int planes = in_sizes[0] / (IMG_H * IMG_W);   // 48

    dim3 block(32, WARPS);                               // 128 threads
    dim3 grid(IMG_W / STRIP_W,                           // 8
              IMG_H / (STRIP_H * WARPS),                 // 4
              planes);                                   // 48
    box5_kernel<<<grid, block>>>(image, out);
}

// round 5
// speedup vs baseline: 1.6260x; 1.1266x over previous
#include <cuda_runtime.h>

#define IMG_H 1024
#define IMG_W 1024
#define STRIP_W 128      // per-warp strip width (32 lanes x float4)
#define STRIP_H 32       // per-warp strip height (output rows)
#define WARPS   4        // warps per block, each an independent y-strip

struct Raw { float4 v; float l2, l1, r0, r1; };

__device__ __forceinline__ int reflect_idx(int g, int n) {
    g = (g < 0) ? -g : g;
    g = (g >= n) ? (2 * n - 2 - g) : g;
    return g;
}

// Pure memory phase: vector load + predicated edge scalars (prefetchable).
__device__ __forceinline__ Raw load_raw(const float* __restrict__ row, int xb,
                                        int lane, int xl2, int xl1,
                                        int xr0, int xr1) {
    Raw t;
    t.v = *reinterpret_cast<const float4*>(row + xb);
    if (lane == 0)  { t.l2 = row[xl2]; t.l1 = row[xl1]; }
    if (lane == 31) { t.r0 = row[xr0]; t.r1 = row[xr1]; }
    return t;
}

// Pure compute phase: shuffles + adds, no memory.
__device__ __forceinline__ float4 hsum_from(const Raw& t, int lane) {
    const float4 v = t.v;
    float lz = __shfl_up_sync(0xFFFFFFFFu, v.z, 1);   // e[x-2]
    float lw = __shfl_up_sync(0xFFFFFFFFu, v.w, 1);   // e[x-1]
    float rx = __shfl_down_sync(0xFFFFFFFFu, v.x, 1); // e[x+4]
    float ry = __shfl_down_sync(0xFFFFFFFFu, v.y, 1); // e[x+5]
    if (lane == 0)  { lz = t.l2; lw = t.l1; }
    if (lane == 31) { rx = t.r0; ry = t.r1; }
    const float c  = v.y + v.z;
    const float s4 = v.x + c + v.w;
    float4 h;
    h.x = lz + lw + v.x + c;
    h.y = lw + s4;
    h.z = s4 + rx;
    h.w = c + v.w + rx + ry;
    return h;
}

__global__ __launch_bounds__(32 * WARPS)
void box5_kernel(const float* __restrict__ in, float* __restrict__ out) {
    const int lane  = threadIdx.x;
    const int plane = blockIdx.z;
    const float* __restrict__ p = in  + (size_t)plane * IMG_H * IMG_W;
    float* __restrict__       o = out + (size_t)plane * IMG_H * IMG_W;

    const int xt = blockIdx.x * STRIP_W;
    const int xb = xt + lane * 4;
    const int y0 = (blockIdx.y * WARPS + threadIdx.y) * STRIP_H;

    const int xl2 = reflect_idx(xt - 2, IMG_W);
    const int xl1 = reflect_idx(xt - 1, IMG_W);
    const int xr0 = reflect_idx(xt + STRIP_W,     IMG_W);
    const int xr1 = reflect_idx(xt + STRIP_W + 1, IMG_W);

    #define ROWP(gy) (p + (size_t)(gy) * IMG_W)

    // Prime: batch 6 independent row loads (y0-2 .. y0+3) before any compute.
    const int gyA = reflect_idx(y0 - 2, IMG_H);
    const int gyB = reflect_idx(y0 - 1, IMG_H);
    Raw ra = load_raw(ROWP(gyA),   xb, lane, xl2, xl1, xr0, xr1);
    Raw rb = load_raw(ROWP(gyB),   xb, lane, xl2, xl1, xr0, xr1);
    Raw rc = load_raw(ROWP(y0),    xb, lane, xl2, xl1, xr0, xr1);
    Raw rd = load_raw(ROWP(y0 + 1), xb, lane, xl2, xl1, xr0, xr1);
    Raw cur = load_raw(ROWP(y0 + 2), xb, lane, xl2, xl1, xr0, xr1);
    Raw nxt = load_raw(ROWP(y0 + 3), xb, lane, xl2, xl1, xr0, xr1);

    float4 h0 = hsum_from(ra, lane);
    float4 h1 = hsum_from(rb, lane);
    float4 h2 = hsum_from(rc, lane);
    float4 h3 = hsum_from(rd, lane);

    float4 vs;
    vs.x = h0.x + h1.x + h2.x + h3.x;
    vs.y = h0.y + h1.y + h2.y + h3.y;
    vs.z = h0.z + h1.z + h2.z + h3.z;
    vs.w = h0.w + h1.w + h2.w + h3.w;

    const float inv25 = 1.0f / 25.0f;

    #pragma unroll 4
    for (int r = 0; r < STRIP_H; ++r) {
        // Prefetch 2 rows ahead (reflect keeps the tail in-bounds; the extra
        // tail rows are the next strip's rows -> L2 hits).
        const int gyF = reflect_idx(y0 + r + 4, IMG_H);
        Raw fut = load_raw(ROWP(gyF), xb, lane, xl2, xl1, xr0, xr1);

        const float4 h4 = hsum_from(cur, lane);

        float4 ov;
        ov.x = (vs.x + h4.x) * inv25;
        ov.y = (vs.y + h4.y) * inv25;
        ov.z = (vs.z + h4.z) * inv25;
        ov.w = (vs.w + h4.w) * inv25;
        *reinterpret_cast<float4*>(o + (size_t)(y0 + r) * IMG_W + xb) = ov;

        vs.x += h4.x - h0.x;
        vs.y += h4.y - h0.y;
        vs.z += h4.z - h0.z;
        vs.w += h4.w - h0.w;
        h0 = h1; h1 = h2; h2 = h3; h3 = h4;
        cur = nxt; nxt = fut;
    }
    #undef ROWP
}

extern "C" void kernel_launch(void* const* d_in, const int* in_sizes, int n_in,
                              void* d_out, int out_size) {
    const float* image = (const float*)d_in[0];
    float* out = (float*)d_out;

    const int planes = in_sizes[0] / (IMG_H * IMG_W);   // 48

    dim3 block(32, WARPS);                               // 128 threads
    dim3 grid(IMG_W / STRIP_W,                           // 8
              IMG_H / (STRIP_H * WARPS),                 // 8
              planes);                                   // 48
    box5_kernel<<<grid, block>>>(image, out);
}